// round 4
// baseline (speedup 1.0000x reference)
#include <cuda_runtime.h>
#include <cuda_bf16.h>
#include <cstdint>

#define H_DIM 1024
#define NSEG  8192
#define NIDX  65536
#define MT    128
#define NT    128
#define KC    32                 // K elems per chunk
#define NCH   (H_DIM / KC)       // 32 chunks
#define NB_TILES (H_DIM / NT)    // 8
#define SROW  80                 // smem row stride bytes (64B data + 16B pad)
#define TILE_BYTES  (128 * SROW)        // 10240
#define STAGE_BYTES (4 * TILE_BYTES)    // 40960
#define SMEM_TOTAL  (2 * STAGE_BYTES)   // 81920

// ---------------- device scratch (no allocs allowed) ----------------
__device__ __nv_bfloat16 g_Ahi[NSEG * H_DIM];   // 16 MB
__device__ __nv_bfloat16 g_Alo[NSEG * H_DIM];   // 16 MB
__device__ __nv_bfloat16 g_Bhi[H_DIM * H_DIM];  // 2 MB
__device__ __nv_bfloat16 g_Blo[H_DIM * H_DIM];  // 2 MB
__device__ float         g_part[NB_TILES * NSEG];

// ---------------- helpers ----------------
__device__ __forceinline__ uint32_t smem_u32(const void* p) {
    uint32_t a;
    asm("{ .reg .u64 t; cvta.to.shared.u64 t, %1; cvt.u32.u64 %0, t; }" : "=r"(a) : "l"(p));
    return a;
}

__device__ __forceinline__ float gelu_f(float x) {
    return 0.5f * x * (1.0f + erff(x * 0.70710678118654752f));
}

#define LDM4(R, addr) \
    asm volatile("ldmatrix.sync.aligned.m8n8.x4.shared.b16 {%0,%1,%2,%3}, [%4];" \
                 : "=r"((R)[0]), "=r"((R)[1]), "=r"((R)[2]), "=r"((R)[3]) : "r"(addr))

#define MMA_BF16(C, A, b0, b1) \
    asm volatile("mma.sync.aligned.m16n8k16.row.col.f32.bf16.bf16.f32 " \
                 "{%0,%1,%2,%3}, {%4,%5,%6,%7}, {%8,%9}, {%0,%1,%2,%3};" \
                 : "+f"((C)[0]), "+f"((C)[1]), "+f"((C)[2]), "+f"((C)[3]) \
                 : "r"((A)[0]), "r"((A)[1]), "r"((A)[2]), "r"((A)[3]), "r"(b0), "r"(b1))

#define CP_ASYNC16(dst, src) \
    asm volatile("cp.async.cg.shared.global [%0], [%1], 16;" :: "r"(dst), "l"(src) : "memory")
#define CP_COMMIT() asm volatile("cp.async.commit_group;" ::: "memory")
#define CP_WAIT1()  asm volatile("cp.async.wait_group 1;" ::: "memory")
#define CP_WAIT0()  asm volatile("cp.async.wait_group 0;" ::: "memory")

// ---------------- kernel 1: segment mean -> bf16 hi/lo split ----------------
__global__ void seg_mean_kernel(const float* __restrict__ hid,
                                const int* __restrict__ indices,
                                const int* __restrict__ seg) {
    int g = blockIdx.x;
    int lo = 0, hi = NIDX;
    while (lo < hi) { int mid = (lo + hi) >> 1; if (seg[mid] < g) lo = mid + 1; else hi = mid; }
    int start = lo;
    hi = NIDX;
    while (lo < hi) { int mid = (lo + hi) >> 1; if (seg[mid] < g + 1) lo = mid + 1; else hi = mid; }
    int end = lo;

    int t = threadIdx.x;  // 256 threads, 4 contiguous cols each
    float4 acc = make_float4(0.f, 0.f, 0.f, 0.f);
    for (int i = start; i < end; ++i) {
        int r = indices[i];
        float4 v = *((const float4*)(hid + (size_t)r * H_DIM) + t);
        acc.x += v.x; acc.y += v.y; acc.z += v.z; acc.w += v.w;
    }
    int cnt = end - start;
    float inv = 1.0f / (float)(cnt > 0 ? cnt : 1);
    float vals[4] = {acc.x * inv, acc.y * inv, acc.z * inv, acc.w * inv};

    size_t base = (size_t)g * H_DIM + t * 4;
#pragma unroll
    for (int j = 0; j < 4; ++j) {
        float v = vals[j];
        __nv_bfloat16 h16 = __float2bfloat16(v);
        float res = v - __bfloat162float(h16);
        g_Ahi[base + j] = h16;
        g_Alo[base + j] = __float2bfloat16(res);
    }
}

// ---------------- kernel 2: W_dense hi/lo split ----------------
__global__ void wsplit_kernel(const float* __restrict__ W) {
    int i = blockIdx.x * blockDim.x + threadIdx.x;
    float v = W[i];
    __nv_bfloat16 h16 = __float2bfloat16(v);
    float res = v - __bfloat162float(h16);
    g_Bhi[i] = h16;
    g_Blo[i] = __float2bfloat16(res);
}

// ---------------- kernel 3: split-bf16 mma.sync GEMM + GELU + proj epilogue ----------------
__device__ __forceinline__ void load_chunk(uint32_t sb, int stage, int kt,
                                           int m0, int n0, int tid) {
#pragma unroll
    for (int j = 0; j < 8; ++j) {
        int tile = j >> 1;                      // constant per j: 0..3
        int rem  = ((j & 1) << 8) + tid;        // 0..511
        int r = rem >> 2, c = rem & 3;
        const __nv_bfloat16* gp;
        if      (tile == 0) gp = g_Ahi + (size_t)(m0 + r) * H_DIM;
        else if (tile == 1) gp = g_Alo + (size_t)(m0 + r) * H_DIM;
        else if (tile == 2) gp = g_Bhi + (size_t)(n0 + r) * H_DIM;
        else                gp = g_Blo + (size_t)(n0 + r) * H_DIM;
        uint32_t dst = sb + stage * STAGE_BYTES + tile * TILE_BYTES + r * SROW + c * 16;
        size_t gsrc = __cvta_generic_to_global((const void*)(gp + kt * KC + c * 8));
        CP_ASYNC16(dst, gsrc);
    }
    CP_COMMIT();
}

__global__ void __launch_bounds__(256)
gemm_kernel(const float* __restrict__ b_dense, const float* __restrict__ W_proj) {
    extern __shared__ char smem_raw[];
    uint32_t sb = smem_u32(smem_raw);
    int tid = threadIdx.x;
    int lane = tid & 31, wid = tid >> 5;
    int wm = wid >> 2, wn = wid & 3;       // 2 x 4 warp grid; warp tile 64(m) x 32(n)
    int nb = blockIdx.x, mb = blockIdx.y;
    int m0 = mb * MT, n0 = nb * NT;

    float acc[4][4][4];
#pragma unroll
    for (int i = 0; i < 4; ++i)
#pragma unroll
        for (int j = 0; j < 4; ++j)
#pragma unroll
            for (int k = 0; k < 4; ++k) acc[i][j][k] = 0.f;

    // per-thread ldmatrix row/col components (x4 address pattern)
    uint32_t a_row = (((lane >> 3) & 1) << 3) + (lane & 7);   // mat0/1 -> rows 0-15
    uint32_t a_kb  = ((lane >> 4) & 1) * 16;                  // mat2/3 -> +8 cols (16B)
    uint32_t b_row = (((lane >> 4) & 1) << 3) + (lane & 7);   // mat0/1 k, mat2/3 n+8
    uint32_t b_kb  = ((lane >> 3) & 1) * 16;

    load_chunk(sb, 0, 0, m0, n0, tid);
    load_chunk(sb, 1, 1, m0, n0, tid);

    for (int kt = 0; kt < NCH; ++kt) {
        if (kt == NCH - 1) { CP_WAIT0(); } else { CP_WAIT1(); }
        __syncthreads();

        uint32_t s0   = sb + (kt & 1) * STAGE_BYTES;
        uint32_t a_hi = s0 + (wm * 64) * SROW;
        uint32_t b_hi = s0 + 2 * TILE_BYTES + (wn * 32) * SROW;

#pragma unroll
        for (int k16 = 0; k16 < 2; ++k16) {
            uint32_t kb = k16 * 32;  // 16 bf16 = 32 bytes
            uint32_t Ah[4][4], Al[4][4], Bh[2][4], Bl[2][4];
#pragma unroll
            for (int mi = 0; mi < 4; ++mi) {
                uint32_t addr = a_hi + (mi * 16 + a_row) * SROW + kb + a_kb;
                LDM4(Ah[mi], addr);
                LDM4(Al[mi], addr + TILE_BYTES);
            }
#pragma unroll
            for (int p = 0; p < 2; ++p) {
                uint32_t addr = b_hi + (p * 16 + b_row) * SROW + kb + b_kb;
                LDM4(Bh[p], addr);
                LDM4(Bl[p], addr + TILE_BYTES);
            }
#pragma unroll
            for (int mi = 0; mi < 4; ++mi)
#pragma unroll
                for (int nj = 0; nj < 4; ++nj) {
                    uint32_t bh0 = Bh[nj >> 1][(nj & 1) * 2], bh1 = Bh[nj >> 1][(nj & 1) * 2 + 1];
                    uint32_t bl0 = Bl[nj >> 1][(nj & 1) * 2], bl1 = Bl[nj >> 1][(nj & 1) * 2 + 1];
                    MMA_BF16(acc[mi][nj], Ah[mi], bh0, bh1);  // hi*hi
                    MMA_BF16(acc[mi][nj], Ah[mi], bl0, bl1);  // hi*lo
                    MMA_BF16(acc[mi][nj], Al[mi], bh0, bh1);  // lo*hi
                }
        }
        __syncthreads();
        if (kt + 2 < NCH) load_chunk(sb, kt & 1, kt + 2, m0, n0, tid);
    }

    // ---- epilogue: bias + exact-erf GELU + dot with W_proj over this CTA's 128 n-cols ----
    int q  = lane >> 2;          // row within 8-group
    int cq = (lane & 3) * 2;     // col pair within n8 tile
    float pr[4][2];
#pragma unroll
    for (int mi = 0; mi < 4; ++mi) { pr[mi][0] = 0.f; pr[mi][1] = 0.f; }

    float bv0[4], bv1[4], wv0[4], wv1[4];
#pragma unroll
    for (int nj = 0; nj < 4; ++nj) {
        int n = n0 + wn * 32 + nj * 8 + cq;
        bv0[nj] = __ldg(b_dense + n);     bv1[nj] = __ldg(b_dense + n + 1);
        wv0[nj] = __ldg(W_proj + n);      wv1[nj] = __ldg(W_proj + n + 1);
    }
#pragma unroll
    for (int mi = 0; mi < 4; ++mi)
#pragma unroll
        for (int nj = 0; nj < 4; ++nj) {
            pr[mi][0] += gelu_f(acc[mi][nj][0] + bv0[nj]) * wv0[nj]
                       + gelu_f(acc[mi][nj][1] + bv1[nj]) * wv1[nj];
            pr[mi][1] += gelu_f(acc[mi][nj][2] + bv0[nj]) * wv0[nj]
                       + gelu_f(acc[mi][nj][3] + bv1[nj]) * wv1[nj];
        }
#pragma unroll
    for (int mi = 0; mi < 4; ++mi) {
#pragma unroll
        for (int s = 1; s <= 2; s <<= 1) {
            pr[mi][0] += __shfl_xor_sync(0xffffffffu, pr[mi][0], s);
            pr[mi][1] += __shfl_xor_sync(0xffffffffu, pr[mi][1], s);
        }
    }

    float* red = (float*)smem_raw;       // 4 (warp_n) x 128 rows, overlays tile smem
    if ((lane & 3) == 0) {
#pragma unroll
        for (int mi = 0; mi < 4; ++mi) {
            int rbase = wm * 64 + mi * 16 + q;
            red[wn * 128 + rbase]     = pr[mi][0];
            red[wn * 128 + rbase + 8] = pr[mi][1];
        }
    }
    __syncthreads();
    if (tid < 128) {
        float s = red[tid] + red[128 + tid] + red[256 + tid] + red[384 + tid];
        g_part[(size_t)nb * NSEG + m0 + tid] = s;
    }
}

// ---------------- kernel 4: deterministic partial reduce + b_proj ----------------
__global__ void final_kernel(const float* __restrict__ b_proj, float* __restrict__ out) {
    int g = blockIdx.x * blockDim.x + threadIdx.x;
    float s = b_proj[0];
#pragma unroll
    for (int nbi = 0; nbi < NB_TILES; ++nbi) s += g_part[(size_t)nbi * NSEG + g];
    out[g] = s;
}

// ---------------- launcher ----------------
extern "C" void kernel_launch(void* const* d_in, const int* in_sizes, int n_in,
                              void* d_out, int out_size) {
    const float* hid     = (const float*)d_in[0];
    const int*   indices = (const int*)d_in[1];
    const int*   seg     = (const int*)d_in[2];
    const float* W_dense = (const float*)d_in[3];
    const float* b_dense = (const float*)d_in[4];
    const float* W_proj  = (const float*)d_in[5];
    const float* b_proj  = (const float*)d_in[6];
    float* out = (float*)d_out;

    cudaFuncSetAttribute(gemm_kernel, cudaFuncAttributeMaxDynamicSharedMemorySize, SMEM_TOTAL);

    seg_mean_kernel<<<NSEG, 256>>>(hid, indices, seg);
    wsplit_kernel<<<(H_DIM * H_DIM) / 256, 256>>>(W_dense);
    gemm_kernel<<<dim3(NB_TILES, NSEG / MT), 256, SMEM_TOTAL>>>(b_dense, W_proj);
    final_kernel<<<NSEG / 256, 256>>>(b_proj, out);
}

// round 5
// speedup vs baseline: 1.0739x; 1.0739x over previous
#include <cuda_runtime.h>
#include <cuda_bf16.h>
#include <cstdint>

#define H_DIM 1024
#define NSEG  8192
#define NIDX  65536
#define MT    128
#define NT    128
#define KC    32                 // K elems per chunk
#define NCH   (H_DIM / KC)       // 32 chunks
#define NB_TILES (H_DIM / NT)    // 8
#define SROW  80                 // smem row stride bytes (64B data + 16B pad)
#define TILE_BYTES  (128 * SROW)        // 10240
#define STAGE_BYTES (4 * TILE_BYTES)    // 40960
#define SMEM_TOTAL  (2 * STAGE_BYTES)   // 81920

// ---------------- device scratch (no allocs allowed) ----------------
__device__ __nv_bfloat16 g_Ahi[NSEG * H_DIM];   // 16 MB
__device__ __nv_bfloat16 g_Alo[NSEG * H_DIM];   // 16 MB
__device__ __nv_bfloat16 g_Bhi[H_DIM * H_DIM];  // 2 MB
__device__ __nv_bfloat16 g_Blo[H_DIM * H_DIM];  // 2 MB
__device__ float         g_part[NB_TILES * NSEG];

// ---------------- helpers ----------------
__device__ __forceinline__ uint32_t smem_u32(const void* p) {
    uint32_t a;
    asm("{ .reg .u64 t; cvta.to.shared.u64 t, %1; cvt.u32.u64 %0, t; }" : "=r"(a) : "l"(p));
    return a;
}

__device__ __forceinline__ float gelu_f(float x) {
    return 0.5f * x * (1.0f + erff(x * 0.70710678118654752f));
}

#define LDM4(R, addr) \
    asm volatile("ldmatrix.sync.aligned.m8n8.x4.shared.b16 {%0,%1,%2,%3}, [%4];" \
                 : "=r"((R)[0]), "=r"((R)[1]), "=r"((R)[2]), "=r"((R)[3]) : "r"(addr))

#define MMA_BF16(C, A, b0, b1) \
    asm volatile("mma.sync.aligned.m16n8k16.row.col.f32.bf16.bf16.f32 " \
                 "{%0,%1,%2,%3}, {%4,%5,%6,%7}, {%8,%9}, {%0,%1,%2,%3};" \
                 : "+f"((C)[0]), "+f"((C)[1]), "+f"((C)[2]), "+f"((C)[3]) \
                 : "r"((A)[0]), "r"((A)[1]), "r"((A)[2]), "r"((A)[3]), "r"(b0), "r"(b1))

#define CP_ASYNC16(dst, src) \
    asm volatile("cp.async.cg.shared.global [%0], [%1], 16;" :: "r"(dst), "l"(src) : "memory")
#define CP_COMMIT() asm volatile("cp.async.commit_group;" ::: "memory")
#define CP_WAIT1()  asm volatile("cp.async.wait_group 1;" ::: "memory")
#define CP_WAIT0()  asm volatile("cp.async.wait_group 0;" ::: "memory")

// ---------------- kernel 1: segment mean -> bf16 hi/lo split ----------------
// 4-way unrolled gather: 4 independent row loads in flight (MLP~4) instead of a
// serial load->add->load chain.
__global__ void seg_mean_kernel(const float* __restrict__ hid,
                                const int* __restrict__ indices,
                                const int* __restrict__ seg) {
    int g = blockIdx.x;
    int lo = 0, hi = NIDX;
    while (lo < hi) { int mid = (lo + hi) >> 1; if (seg[mid] < g) lo = mid + 1; else hi = mid; }
    int start = lo;
    hi = NIDX;
    while (lo < hi) { int mid = (lo + hi) >> 1; if (seg[mid] < g + 1) lo = mid + 1; else hi = mid; }
    int end = lo;

    int t = threadIdx.x;  // 256 threads, 4 contiguous cols each
    float4 acc = make_float4(0.f, 0.f, 0.f, 0.f);

    int i = start;
    for (; i + 4 <= end; i += 4) {
        int r0 = __ldg(indices + i);
        int r1 = __ldg(indices + i + 1);
        int r2 = __ldg(indices + i + 2);
        int r3 = __ldg(indices + i + 3);
        float4 v0 = __ldg((const float4*)(hid + (size_t)r0 * H_DIM) + t);
        float4 v1 = __ldg((const float4*)(hid + (size_t)r1 * H_DIM) + t);
        float4 v2 = __ldg((const float4*)(hid + (size_t)r2 * H_DIM) + t);
        float4 v3 = __ldg((const float4*)(hid + (size_t)r3 * H_DIM) + t);
        acc.x += v0.x; acc.y += v0.y; acc.z += v0.z; acc.w += v0.w;
        acc.x += v1.x; acc.y += v1.y; acc.z += v1.z; acc.w += v1.w;
        acc.x += v2.x; acc.y += v2.y; acc.z += v2.z; acc.w += v2.w;
        acc.x += v3.x; acc.y += v3.y; acc.z += v3.z; acc.w += v3.w;
    }
    for (; i < end; ++i) {
        int r = __ldg(indices + i);
        float4 v = __ldg((const float4*)(hid + (size_t)r * H_DIM) + t);
        acc.x += v.x; acc.y += v.y; acc.z += v.z; acc.w += v.w;
    }

    int cnt = end - start;
    float inv = 1.0f / (float)(cnt > 0 ? cnt : 1);
    float vals[4] = {acc.x * inv, acc.y * inv, acc.z * inv, acc.w * inv};

    size_t base = (size_t)g * H_DIM + t * 4;
#pragma unroll
    for (int j = 0; j < 4; ++j) {
        float v = vals[j];
        __nv_bfloat16 h16 = __float2bfloat16(v);
        float res = v - __bfloat162float(h16);
        g_Ahi[base + j] = h16;
        g_Alo[base + j] = __float2bfloat16(res);
    }
}

// ---------------- kernel 2: W_dense hi/lo split ----------------
__global__ void wsplit_kernel(const float* __restrict__ W) {
    int i = blockIdx.x * blockDim.x + threadIdx.x;
    float v = W[i];
    __nv_bfloat16 h16 = __float2bfloat16(v);
    float res = v - __bfloat162float(h16);
    g_Bhi[i] = h16;
    g_Blo[i] = __float2bfloat16(res);
}

// ---------------- kernel 3: split-bf16 mma.sync GEMM + GELU + proj epilogue ----------------
__device__ __forceinline__ void load_chunk(uint32_t sb, int stage, int kt,
                                           int m0, int n0, int tid) {
#pragma unroll
    for (int j = 0; j < 8; ++j) {
        int tile = j >> 1;                      // constant per j: 0..3
        int rem  = ((j & 1) << 8) + tid;        // 0..511
        int r = rem >> 2, c = rem & 3;
        const __nv_bfloat16* gp;
        if      (tile == 0) gp = g_Ahi + (size_t)(m0 + r) * H_DIM;
        else if (tile == 1) gp = g_Alo + (size_t)(m0 + r) * H_DIM;
        else if (tile == 2) gp = g_Bhi + (size_t)(n0 + r) * H_DIM;
        else                gp = g_Blo + (size_t)(n0 + r) * H_DIM;
        uint32_t dst = sb + stage * STAGE_BYTES + tile * TILE_BYTES + r * SROW + c * 16;
        size_t gsrc = __cvta_generic_to_global((const void*)(gp + kt * KC + c * 8));
        CP_ASYNC16(dst, gsrc);
    }
    CP_COMMIT();
}

__global__ void __launch_bounds__(256, 2)
gemm_kernel(const float* __restrict__ b_dense, const float* __restrict__ W_proj) {
    extern __shared__ char smem_raw[];
    uint32_t sb = smem_u32(smem_raw);
    int tid = threadIdx.x;
    int lane = tid & 31, wid = tid >> 5;
    int wm = wid >> 2, wn = wid & 3;       // 2 x 4 warp grid; warp tile 64(m) x 32(n)
    int nb = blockIdx.x, mb = blockIdx.y;
    int m0 = mb * MT, n0 = nb * NT;

    float acc[4][4][4];
#pragma unroll
    for (int i = 0; i < 4; ++i)
#pragma unroll
        for (int j = 0; j < 4; ++j)
#pragma unroll
            for (int k = 0; k < 4; ++k) acc[i][j][k] = 0.f;

    // per-thread ldmatrix row/col components (x4 address pattern)
    uint32_t a_row = (((lane >> 3) & 1) << 3) + (lane & 7);   // mat0/1 -> rows 0-15
    uint32_t a_kb  = ((lane >> 4) & 1) * 16;                  // mat2/3 -> +8 cols (16B)
    uint32_t b_row = (((lane >> 4) & 1) << 3) + (lane & 7);   // mat0/1 k, mat2/3 n+8
    uint32_t b_kb  = ((lane >> 3) & 1) * 16;

    load_chunk(sb, 0, 0, m0, n0, tid);
    load_chunk(sb, 1, 1, m0, n0, tid);

    for (int kt = 0; kt < NCH; ++kt) {
        if (kt == NCH - 1) { CP_WAIT0(); } else { CP_WAIT1(); }
        __syncthreads();

        uint32_t s0   = sb + (kt & 1) * STAGE_BYTES;
        uint32_t a_hi = s0 + (wm * 64) * SROW;
        uint32_t b_hi = s0 + 2 * TILE_BYTES + (wn * 32) * SROW;

#pragma unroll
        for (int k16 = 0; k16 < 2; ++k16) {
            uint32_t kb = k16 * 32;  // 16 bf16 = 32 bytes

            // B frags first (small: 16 regs live), A streamed per-mi (8 regs live)
            uint32_t Bh[2][4], Bl[2][4];
#pragma unroll
            for (int p = 0; p < 2; ++p) {
                uint32_t addr = b_hi + (p * 16 + b_row) * SROW + kb + b_kb;
                LDM4(Bh[p], addr);
                LDM4(Bl[p], addr + TILE_BYTES);
            }
#pragma unroll
            for (int mi = 0; mi < 4; ++mi) {
                uint32_t Ah[4], Al[4];
                uint32_t addr = a_hi + (mi * 16 + a_row) * SROW + kb + a_kb;
                LDM4(Ah, addr);
                LDM4(Al, addr + TILE_BYTES);
#pragma unroll
                for (int nj = 0; nj < 4; ++nj) {
                    uint32_t bh0 = Bh[nj >> 1][(nj & 1) * 2], bh1 = Bh[nj >> 1][(nj & 1) * 2 + 1];
                    uint32_t bl0 = Bl[nj >> 1][(nj & 1) * 2], bl1 = Bl[nj >> 1][(nj & 1) * 2 + 1];
                    MMA_BF16(acc[mi][nj], Ah, bh0, bh1);  // hi*hi
                    MMA_BF16(acc[mi][nj], Ah, bl0, bl1);  // hi*lo
                    MMA_BF16(acc[mi][nj], Al, bh0, bh1);  // lo*hi
                }
            }
        }
        __syncthreads();
        if (kt + 2 < NCH) load_chunk(sb, kt & 1, kt + 2, m0, n0, tid);
    }

    // ---- epilogue: bias + exact-erf GELU + dot with W_proj over this CTA's 128 n-cols ----
    int q  = lane >> 2;          // row within 8-group
    int cq = (lane & 3) * 2;     // col pair within n8 tile
    float pr[4][2];
#pragma unroll
    for (int mi = 0; mi < 4; ++mi) { pr[mi][0] = 0.f; pr[mi][1] = 0.f; }

    float bv0[4], bv1[4], wv0[4], wv1[4];
#pragma unroll
    for (int nj = 0; nj < 4; ++nj) {
        int n = n0 + wn * 32 + nj * 8 + cq;
        bv0[nj] = __ldg(b_dense + n);     bv1[nj] = __ldg(b_dense + n + 1);
        wv0[nj] = __ldg(W_proj + n);      wv1[nj] = __ldg(W_proj + n + 1);
    }
#pragma unroll
    for (int mi = 0; mi < 4; ++mi)
#pragma unroll
        for (int nj = 0; nj < 4; ++nj) {
            pr[mi][0] += gelu_f(acc[mi][nj][0] + bv0[nj]) * wv0[nj]
                       + gelu_f(acc[mi][nj][1] + bv1[nj]) * wv1[nj];
            pr[mi][1] += gelu_f(acc[mi][nj][2] + bv0[nj]) * wv0[nj]
                       + gelu_f(acc[mi][nj][3] + bv1[nj]) * wv1[nj];
        }
#pragma unroll
    for (int mi = 0; mi < 4; ++mi) {
#pragma unroll
        for (int s = 1; s <= 2; s <<= 1) {
            pr[mi][0] += __shfl_xor_sync(0xffffffffu, pr[mi][0], s);
            pr[mi][1] += __shfl_xor_sync(0xffffffffu, pr[mi][1], s);
        }
    }

    float* red = (float*)smem_raw;       // 4 (warp_n) x 128 rows, overlays tile smem
    __syncthreads();
    if ((lane & 3) == 0) {
#pragma unroll
        for (int mi = 0; mi < 4; ++mi) {
            int rbase = wm * 64 + mi * 16 + q;
            red[wn * 128 + rbase]     = pr[mi][0];
            red[wn * 128 + rbase + 8] = pr[mi][1];
        }
    }
    __syncthreads();
    if (tid < 128) {
        float s = red[tid] + red[128 + tid] + red[256 + tid] + red[384 + tid];
        g_part[(size_t)nb * NSEG + m0 + tid] = s;
    }
}

// ---------------- kernel 4: deterministic partial reduce + b_proj ----------------
__global__ void final_kernel(const float* __restrict__ b_proj, float* __restrict__ out) {
    int g = blockIdx.x * blockDim.x + threadIdx.x;
    float s = b_proj[0];
#pragma unroll
    for (int nbi = 0; nbi < NB_TILES; ++nbi) s += g_part[(size_t)nbi * NSEG + g];
    out[g] = s;
}

// ---------------- launcher ----------------
extern "C" void kernel_launch(void* const* d_in, const int* in_sizes, int n_in,
                              void* d_out, int out_size) {
    const float* hid     = (const float*)d_in[0];
    const int*   indices = (const int*)d_in[1];
    const int*   seg     = (const int*)d_in[2];
    const float* W_dense = (const float*)d_in[3];
    const float* b_dense = (const float*)d_in[4];
    const float* W_proj  = (const float*)d_in[5];
    const float* b_proj  = (const float*)d_in[6];
    float* out = (float*)d_out;

    cudaFuncSetAttribute(gemm_kernel, cudaFuncAttributeMaxDynamicSharedMemorySize, SMEM_TOTAL);

    seg_mean_kernel<<<NSEG, 256>>>(hid, indices, seg);
    wsplit_kernel<<<(H_DIM * H_DIM) / 256, 256>>>(W_dense);
    gemm_kernel<<<dim3(NB_TILES, NSEG / MT), 256, SMEM_TOTAL>>>(b_dense, W_proj);
    final_kernel<<<NSEG / 256, 256>>>(b_proj, out);
}